// round 8
// baseline (speedup 1.0000x reference)
#include <cuda_runtime.h>
#include <cuda_bf16.h>
#include <cuda_fp16.h>
#include <cstdint>
#include <cstddef>

// Problem shape (fixed by reference): B=16, T=1024, D=256
#define BB 16
#define TT 1024
#define DD 256

#define TILE 128      // (t,s) tile per CTA
#define KC   32       // K chunk staged through smem
#define STRIDE 40     // bf16 units per smem row (32+8 pad): conflict-free, rows 16B-aligned
#define WSTR 136      // fp16 units per w-smem row (128+8 pad): conflict-free combine reads

#define C_YX 61.72839506172839f   // 1/(2*0.09^2)
#define C_HW 5.555555555555555f   // 1/(2*0.3^2)

// dynamic smem layout (bytes)
#define SMEM_A   0                      // 2 bufs * 128*40*2 = 20480
#define SMEM_B   20480                  // 2 bufs * 128*40*2 = 20480
#define SMEM_W   40960                  // 128*136*2 = 34816
#define SMEM_RED 75776                  // 24 floats
#define SMEM_TOTAL 75904

__device__ float g_num[BB];
__device__ float g_den[BB];
__device__ __nv_bfloat16 g_zb[BB * TT * DD];   // bf16 copy of z (8.4 MB scratch)

__device__ __forceinline__ void cp16(void* dst, const void* src) {
    uint32_t d = (uint32_t)__cvta_generic_to_shared(dst);
    asm volatile("cp.async.cg.shared.global [%0], [%1], 16;\n" :: "r"(d), "l"(src));
}

__device__ __forceinline__ void mma_bf16(float c[4], const uint32_t a[4], const uint32_t b[2]) {
    asm volatile(
        "mma.sync.aligned.m16n8k16.row.col.f32.bf16.bf16.f32 "
        "{%0,%1,%2,%3}, {%4,%5,%6,%7}, {%8,%9}, {%0,%1,%2,%3};"
        : "+f"(c[0]), "+f"(c[1]), "+f"(c[2]), "+f"(c[3])
        : "r"(a[0]), "r"(a[1]), "r"(a[2]), "r"(a[3]), "r"(b[0]), "r"(b[1]));
}

__device__ __forceinline__ void ldsm_x4(uint32_t r[4], uint32_t a) {
    asm volatile("ldmatrix.sync.aligned.m8n8.x4.shared.b16 {%0,%1,%2,%3}, [%4];"
        : "=r"(r[0]), "=r"(r[1]), "=r"(r[2]), "=r"(r[3]) : "r"(a));
}
__device__ __forceinline__ void ldsm_x2(uint32_t r[2], uint32_t a) {
    asm volatile("ldmatrix.sync.aligned.m8n8.x2.shared.b16 {%0,%1}, [%2];"
        : "=r"(r[0]), "=r"(r[1]) : "r"(a));
}

// ---------------------------------------------------------------------------
// Prep: z (fp32) -> g_zb (bf16) streaming convert; zero accumulators.
// 256 blocks x 256 threads, 16 float4 per thread, fully coalesced.
// ---------------------------------------------------------------------------
__global__ void prep_kernel(const float4* __restrict__ z4) {
    if (blockIdx.x == 0 && threadIdx.x < BB) {
        g_num[threadIdx.x] = 0.0f;
        g_den[threadIdx.x] = 0.0f;
    }
    int base = blockIdx.x * 256 + threadIdx.x;
#pragma unroll
    for (int i = 0; i < 16; i++) {
        int idx = base + i * 65536;
        float4 v = z4[idx];
        __nv_bfloat162 lo = __floats2bfloat162_rn(v.x, v.y);
        __nv_bfloat162 hi = __floats2bfloat162_rn(v.z, v.w);
        uint2 pk;
        pk.x = *(uint32_t*)&lo;
        pk.y = *(uint32_t*)&hi;
        *(uint2*)(g_zb + (size_t)idx * 4) = pk;
    }
}

// ---------------------------------------------------------------------------
// Fused, warp-specialized: warps 0-7 = bf16 MMA (Gram tile, cp.async pipe,
// named barrier 1), warps 8-15 = dT streamers (w -> fp16 smem, Sum w).
// After mainloop, MMA warps stream the last 16 rows, join, then combine
// Sum(w*G) against their accumulators. num = 2*Sum(w) - 2*Sum(w*G) (z2==1).
// grid = (T/TILE, T/TILE, B), block = 512.
// ---------------------------------------------------------------------------
__global__ __launch_bounds__(512, 1)
void fused_kernel(const float4* __restrict__ dT4) {
    extern __shared__ char sm[];
    __nv_bfloat16* smA = (__nv_bfloat16*)(sm + SMEM_A);
    __nv_bfloat16* smB = (__nv_bfloat16*)(sm + SMEM_B);
    __half*        smW = (__half*)(sm + SMEM_W);
    float*         red = (float*)(sm + SMEM_RED);

    const int b  = blockIdx.z;
    const int t0 = blockIdx.y * TILE;
    const int s0 = blockIdx.x * TILE;

    const int tid  = threadIdx.x;
    const int warp = tid >> 5;
    const int lane = tid & 31;

    const size_t dbase = (size_t)b * TT * TT + (size_t)t0 * TT + s0;

    float sum_w = 0.0f;
    float acc[16][4];

    if (warp >= 8) {
        // ================= streamer warps: rows 0..111 (14 per warp) =========
        const int mw = warp - 8;
#pragma unroll 2
        for (int r = 0; r < 14; r++) {
            const int row = mw * 14 + r;
            const float4* p = dT4 + dbase + (size_t)row * TT;
            __half* wrow = smW + row * WSTR;
#pragma unroll
            for (int it = 0; it < 4; it++) {
                float4 d = __ldg(p + it * 32 + lane);
                float e = (d.x * d.x + d.y * d.y) * C_YX
                        + (d.z * d.z + d.w * d.w) * C_HW;
                float w = __expf(-e);
                sum_w += w;
                wrow[it * 32 + lane] = __float2half_rn(w);
            }
        }
    } else {
        // ================= MMA warps: Gram tile via bf16 mma ==================
        const int wm = warp & 1;   // row half (64 rows)
        const int wn = warp >> 1;  // col quarter (32 cols)

        const __nv_bfloat16* zbA = g_zb + (size_t)b * TT * DD + (size_t)t0 * DD;
        const __nv_bfloat16* zbB = g_zb + (size_t)b * TT * DD + (size_t)s0 * DD;

        // staging coords: 256 threads cover one 128x32 bf16 tile as 16B units
        const int sr0 = tid >> 2, sc0 = tid & 3;
        const int sr1 = (tid + 256) >> 2, sc1 = (tid + 256) & 3;

        // ldmatrix per-lane byte offsets within a buffer
        const uint32_t smA_u = (uint32_t)__cvta_generic_to_shared(smA);
        const uint32_t smB_u = (uint32_t)__cvta_generic_to_shared(smB);
        uint32_t offA[4], offB[4];
        {
            const int rowA = lane & 15;
            const int colA = (lane >> 4) << 3;
#pragma unroll
            for (int mi = 0; mi < 4; mi++)
                offA[mi] = ((wm * 64 + mi * 16 + rowA) * STRIDE + colA) * 2;
            const int rowB = lane & 7;
            const int colB = ((lane >> 3) & 1) << 3;
#pragma unroll
            for (int ni = 0; ni < 4; ni++)
                offB[ni] = ((wn * 32 + ni * 8 + rowB) * STRIDE + colB) * 2;
        }

#pragma unroll
        for (int i = 0; i < 16; i++)
#pragma unroll
            for (int j = 0; j < 4; j++) acc[i][j] = 0.0f;

        // prologue: stage chunk 0 into buffer 0
        cp16(&smA[sr0 * STRIDE + sc0 * 8], zbA + (size_t)sr0 * DD + sc0 * 8);
        cp16(&smB[sr0 * STRIDE + sc0 * 8], zbB + (size_t)sr0 * DD + sc0 * 8);
        cp16(&smA[sr1 * STRIDE + sc1 * 8], zbA + (size_t)sr1 * DD + sc1 * 8);
        cp16(&smB[sr1 * STRIDE + sc1 * 8], zbB + (size_t)sr1 * DD + sc1 * 8);
        asm volatile("cp.async.commit_group;\n" ::);

#pragma unroll
        for (int kci = 0; kci < DD / KC; kci++) {
            const int cb = kci & 1;
            if (kci < DD / KC - 1) {
                const int kn = (kci + 1) * KC;
                const int nb = (kci + 1) & 1;
                __nv_bfloat16* dA = smA + nb * (TILE * STRIDE);
                __nv_bfloat16* dB = smB + nb * (TILE * STRIDE);
                cp16(&dA[sr0 * STRIDE + sc0 * 8], zbA + (size_t)sr0 * DD + kn + sc0 * 8);
                cp16(&dB[sr0 * STRIDE + sc0 * 8], zbB + (size_t)sr0 * DD + kn + sc0 * 8);
                cp16(&dA[sr1 * STRIDE + sc1 * 8], zbA + (size_t)sr1 * DD + kn + sc1 * 8);
                cp16(&dB[sr1 * STRIDE + sc1 * 8], zbB + (size_t)sr1 * DD + kn + sc1 * 8);
                asm volatile("cp.async.commit_group;\n" ::);
                asm volatile("cp.async.wait_group 1;\n" ::);
            } else {
                asm volatile("cp.async.wait_group 0;\n" ::);
            }
            asm volatile("bar.sync 1, 256;\n" ::: "memory");

            const uint32_t bufA = smA_u + cb * (TILE * STRIDE * 2);
            const uint32_t bufB = smB_u + cb * (TILE * STRIDE * 2);
#pragma unroll
            for (int k0 = 0; k0 < KC; k0 += 16) {
                uint32_t af[4][4], bf[4][2];
#pragma unroll
                for (int mi = 0; mi < 4; mi++) ldsm_x4(af[mi], bufA + offA[mi] + k0 * 2);
#pragma unroll
                for (int ni = 0; ni < 4; ni++) ldsm_x2(bf[ni], bufB + offB[ni] + k0 * 2);
#pragma unroll
                for (int mi = 0; mi < 4; mi++)
#pragma unroll
                    for (int ni = 0; ni < 4; ni++)
                        mma_bf16(acc[mi * 4 + ni], af[mi], bf[ni]);
            }
            asm volatile("bar.sync 1, 256;\n" ::: "memory");
        }

        // ---- MMA warps take the remaining 16 dT rows (112..127) -------------
#pragma unroll
        for (int r = 0; r < 2; r++) {
            const int row = 112 + warp * 2 + r;
            const float4* p = dT4 + dbase + (size_t)row * TT;
            __half* wrow = smW + row * WSTR;
#pragma unroll
            for (int it = 0; it < 4; it++) {
                float4 d = __ldg(p + it * 32 + lane);
                float e = (d.x * d.x + d.y * d.y) * C_YX
                        + (d.z * d.z + d.w * d.w) * C_HW;
                float w = __expf(-e);
                sum_w += w;
                wrow[it * 32 + lane] = __float2half_rn(w);
            }
        }
    }

    // per-warp reduce of streamed Sum(w)
#pragma unroll
    for (int o = 16; o > 0; o >>= 1) sum_w += __shfl_down_sync(0xFFFFFFFFu, sum_w, o);
    if (lane == 0) red[warp] = sum_w;

    __syncthreads();   // join: w tile complete + all acc done

    // ---- combine: Sum(w*G) on the MMA warps' fragments ----------------------
    if (warp < 8) {
        const int wm = warp & 1;
        const int wn = warp >> 1;
        const int g  = lane >> 2;
        const int tg = lane & 3;
        float sum_wg = 0.0f;
#pragma unroll
        for (int mi = 0; mi < 4; mi++) {
            const int tt = wm * 64 + mi * 16 + g;
#pragma unroll
            for (int ni = 0; ni < 4; ni++) {
                const int ss = wn * 32 + ni * 8 + 2 * tg;
                const float* a = acc[mi * 4 + ni];
                float2 f0 = __half22float2(*(const __half2*)&smW[tt * WSTR + ss]);
                float2 f1 = __half22float2(*(const __half2*)&smW[(tt + 8) * WSTR + ss]);
                sum_wg += f0.x * a[0] + f0.y * a[1] + f1.x * a[2] + f1.y * a[3];
            }
        }
#pragma unroll
        for (int o = 16; o > 0; o >>= 1) sum_wg += __shfl_down_sync(0xFFFFFFFFu, sum_wg, o);
        if (lane == 0) red[16 + warp] = sum_wg;
    }
    __syncthreads();

    if (tid == 0) {
        float W = 0.0f, WG = 0.0f;
#pragma unroll
        for (int i = 0; i < 16; i++) W += red[i];
#pragma unroll
        for (int i = 0; i < 8; i++) WG += red[16 + i];
        atomicAdd(&g_den[b], W);
        atomicAdd(&g_num[b], 2.0f * (W - WG));
    }
}

// ---------------------------------------------------------------------------
// Finalize: mean over batches of num / max(den, 1e-6)
// ---------------------------------------------------------------------------
__global__ void final_kernel(float* __restrict__ out) {
    int lane = threadIdx.x;
    float r = 0.0f;
    if (lane < BB) r = g_num[lane] / fmaxf(g_den[lane], 1e-6f);
#pragma unroll
    for (int o = 16; o > 0; o >>= 1) r += __shfl_down_sync(0xFFFFFFFFu, r, o);
    if (lane == 0) out[0] = r * (1.0f / BB);
}

extern "C" void kernel_launch(void* const* d_in, const int* in_sizes, int n_in,
                              void* d_out, int out_size) {
    const float* z  = (const float*)d_in[0];
    const float* dT = (const float*)d_in[1];
    // Defensive: z has B*T*D = 4.19M elems, gt_dT has B*T*T*4 = 67.1M.
    if (n_in >= 2 && in_sizes[0] > in_sizes[1]) {
        const float* tmp = z; z = dT; dT = tmp;
    }
    (void)out_size;

    cudaFuncSetAttribute(fused_kernel,
                         cudaFuncAttributeMaxDynamicSharedMemorySize, SMEM_TOTAL);

    prep_kernel<<<256, 256>>>((const float4*)z);

    dim3 grid(TT / TILE, TT / TILE, BB);
    fused_kernel<<<grid, 512, SMEM_TOTAL>>>((const float4*)dT);

    final_kernel<<<1, 32>>>((float*)d_out);
}

// round 9
// speedup vs baseline: 1.0964x; 1.0964x over previous
#include <cuda_runtime.h>
#include <cuda_bf16.h>
#include <cuda_fp16.h>
#include <cstdint>
#include <cstddef>

// Problem shape (fixed by reference): B=16, T=1024, D=256
#define BB 16
#define TT 1024
#define DD 256

#define TILE 128      // (t,s) tile per CTA
#define NT   8        // TT/TILE
#define NPAIR 36      // upper-triangular tile pairs per batch
#define KC   32       // K chunk staged through smem
#define STRIDE 40     // bf16 units per smem row (32+8 pad): conflict-free, rows 16B-aligned
#define WSTR 136      // fp16 units per w-smem row (128+8 pad)

#define C_YX 61.72839506172839f   // 1/(2*0.09^2)
#define C_HW 5.555555555555555f   // 1/(2*0.3^2)

// dynamic smem: A(2 bufs)=20480B | B(2 bufs)=20480B ; w-tile (34816B) overlays A+B
#define SMEM_B_OFF 20480
#define SMEM_RED   40960
#define SMEM_TOTAL 41088

__device__ float g_num[BB];
__device__ float g_den[BB];
__device__ __nv_bfloat16 g_zb[BB * TT * DD];   // bf16 copy of z (8.4 MB scratch)

__device__ __forceinline__ void cp16(void* dst, const void* src) {
    uint32_t d = (uint32_t)__cvta_generic_to_shared(dst);
    asm volatile("cp.async.cg.shared.global [%0], [%1], 16;\n" :: "r"(d), "l"(src));
}

__device__ __forceinline__ void mma_bf16(float c[4], const uint32_t a[4], const uint32_t b[2]) {
    asm volatile(
        "mma.sync.aligned.m16n8k16.row.col.f32.bf16.bf16.f32 "
        "{%0,%1,%2,%3}, {%4,%5,%6,%7}, {%8,%9}, {%0,%1,%2,%3};"
        : "+f"(c[0]), "+f"(c[1]), "+f"(c[2]), "+f"(c[3])
        : "r"(a[0]), "r"(a[1]), "r"(a[2]), "r"(a[3]), "r"(b[0]), "r"(b[1]));
}

__device__ __forceinline__ void ldsm_x4(uint32_t r[4], uint32_t a) {
    asm volatile("ldmatrix.sync.aligned.m8n8.x4.shared.b16 {%0,%1,%2,%3}, [%4];"
        : "=r"(r[0]), "=r"(r[1]), "=r"(r[2]), "=r"(r[3]) : "r"(a));
}
__device__ __forceinline__ void ldsm_x2(uint32_t r[2], uint32_t a) {
    asm volatile("ldmatrix.sync.aligned.m8n8.x2.shared.b16 {%0,%1}, [%2];"
        : "=r"(r[0]), "=r"(r[1]) : "r"(a));
}

// ---------------------------------------------------------------------------
// Prep: z (fp32) -> g_zb (bf16); zero accumulators. 1024x256, 4 float4/thread.
// ---------------------------------------------------------------------------
__global__ void prep_kernel(const float4* __restrict__ z4) {
    if (blockIdx.x == 0 && threadIdx.x < BB) {
        g_num[threadIdx.x] = 0.0f;
        g_den[threadIdx.x] = 0.0f;
    }
    int base = blockIdx.x * 1024 + threadIdx.x;
#pragma unroll
    for (int i = 0; i < 4; i++) {
        int idx = base + i * 256;
        float4 v = z4[idx];
        __nv_bfloat162 lo = __floats2bfloat162_rn(v.x, v.y);
        __nv_bfloat162 hi = __floats2bfloat162_rn(v.z, v.w);
        uint2 pk;
        pk.x = *(uint32_t*)&lo;
        pk.y = *(uint32_t*)&hi;
        *(uint2*)(g_zb + (size_t)idx * 4) = pk;
    }
}

// ---------------------------------------------------------------------------
// Fused, symmetric-tiled: one CTA per upper-triangular (i,j) tile pair.
//  Phase 1: Gram tile G (bf16 mma, cp.async double-buffered).
//  Phase 2: stream dT(i,j) -> w (fp16, smem overlay), Sum w; combine Sum(w*G).
//  Phase 3 (i!=j): same for dT(j,i) against G^T (fragment reads transposed).
//  num = 2*Sum(w) - 2*Sum(w*G)  (z is L2-normalized -> z2 == 1).
// grid = B*36, block = 256 (8 warps; 2x4 warp grid, 64x32 per warp).
// ---------------------------------------------------------------------------
__global__ __launch_bounds__(256, 2)
void fused_kernel(const float4* __restrict__ dT4) {
    extern __shared__ char sm[];
    __nv_bfloat16* smA = (__nv_bfloat16*)(sm);
    __nv_bfloat16* smB = (__nv_bfloat16*)(sm + SMEM_B_OFF);
    __half*        smW = (__half*)(sm);                 // overlays A+B after GEMM
    float*         red = (float*)(sm + SMEM_RED);

    // decode (b, i<=j) from linear block id
    const int b = blockIdx.x / NPAIR;
    int rem = blockIdx.x % NPAIR;
    int ti = 0;
    while (rem >= NT - ti) { rem -= NT - ti; ti++; }
    const int tj = ti + rem;
    const int t0 = ti * TILE;
    const int s0 = tj * TILE;

    const int tid  = threadIdx.x;
    const int warp = tid >> 5;
    const int lane = tid & 31;
    const int wm   = warp & 1;   // row half (64 rows)
    const int wn   = warp >> 1;  // col quarter (32 cols)
    const int g    = lane >> 2;
    const int tg   = lane & 3;

    // ================= Phase 1: Gram tile ====================================
    const __nv_bfloat16* zbA = g_zb + (size_t)b * TT * DD + (size_t)t0 * DD;
    const __nv_bfloat16* zbB = g_zb + (size_t)b * TT * DD + (size_t)s0 * DD;

    const int sr0 = tid >> 2, sc0 = tid & 3;
    const int sr1 = (tid + 256) >> 2, sc1 = (tid + 256) & 3;

    const uint32_t smA_u = (uint32_t)__cvta_generic_to_shared(smA);
    const uint32_t smB_u = (uint32_t)__cvta_generic_to_shared(smB);
    uint32_t offA[4], offB[4];
    {
        const int rowA = lane & 15;
        const int colA = (lane >> 4) << 3;
#pragma unroll
        for (int mi = 0; mi < 4; mi++)
            offA[mi] = ((wm * 64 + mi * 16 + rowA) * STRIDE + colA) * 2;
        const int rowB = lane & 7;
        const int colB = ((lane >> 3) & 1) << 3;
#pragma unroll
        for (int ni = 0; ni < 4; ni++)
            offB[ni] = ((wn * 32 + ni * 8 + rowB) * STRIDE + colB) * 2;
    }

    float acc[16][4];
#pragma unroll
    for (int i = 0; i < 16; i++)
#pragma unroll
        for (int j = 0; j < 4; j++) acc[i][j] = 0.0f;

    cp16(&smA[sr0 * STRIDE + sc0 * 8], zbA + (size_t)sr0 * DD + sc0 * 8);
    cp16(&smB[sr0 * STRIDE + sc0 * 8], zbB + (size_t)sr0 * DD + sc0 * 8);
    cp16(&smA[sr1 * STRIDE + sc1 * 8], zbA + (size_t)sr1 * DD + sc1 * 8);
    cp16(&smB[sr1 * STRIDE + sc1 * 8], zbB + (size_t)sr1 * DD + sc1 * 8);
    asm volatile("cp.async.commit_group;\n" ::);

#pragma unroll
    for (int kci = 0; kci < DD / KC; kci++) {
        const int cb = kci & 1;
        if (kci < DD / KC - 1) {
            const int kn = (kci + 1) * KC;
            const int nb = (kci + 1) & 1;
            __nv_bfloat16* dA = smA + nb * (TILE * STRIDE);
            __nv_bfloat16* dB = smB + nb * (TILE * STRIDE);
            cp16(&dA[sr0 * STRIDE + sc0 * 8], zbA + (size_t)sr0 * DD + kn + sc0 * 8);
            cp16(&dB[sr0 * STRIDE + sc0 * 8], zbB + (size_t)sr0 * DD + kn + sc0 * 8);
            cp16(&dA[sr1 * STRIDE + sc1 * 8], zbA + (size_t)sr1 * DD + kn + sc1 * 8);
            cp16(&dB[sr1 * STRIDE + sc1 * 8], zbB + (size_t)sr1 * DD + kn + sc1 * 8);
            asm volatile("cp.async.commit_group;\n" ::);
            asm volatile("cp.async.wait_group 1;\n" ::);
        } else {
            asm volatile("cp.async.wait_group 0;\n" ::);
        }
        __syncthreads();

        const uint32_t bufA = smA_u + cb * (TILE * STRIDE * 2);
        const uint32_t bufB = smB_u + cb * (TILE * STRIDE * 2);
#pragma unroll
        for (int k0 = 0; k0 < KC; k0 += 16) {
            uint32_t af[4][4], bf[4][2];
#pragma unroll
            for (int mi = 0; mi < 4; mi++) ldsm_x4(af[mi], bufA + offA[mi] + k0 * 2);
#pragma unroll
            for (int ni = 0; ni < 4; ni++) ldsm_x2(bf[ni], bufB + offB[ni] + k0 * 2);
#pragma unroll
            for (int mi = 0; mi < 4; mi++)
#pragma unroll
                for (int ni = 0; ni < 4; ni++)
                    mma_bf16(acc[mi * 4 + ni], af[mi], bf[ni]);
        }
        __syncthreads();
    }

    float sum_w = 0.0f, sum_wg = 0.0f;

    // ================= Phase 2: direct tile dT(i,j) ==========================
    {
        const size_t dbase = (size_t)b * TT * TT + (size_t)t0 * TT + s0;
#pragma unroll 4
        for (int r = 0; r < 16; r++) {
            const int row = warp * 16 + r;
            const float4* p = dT4 + dbase + (size_t)row * TT;
            __half* wrow = smW + row * WSTR;
#pragma unroll
            for (int it = 0; it < 4; it++) {
                float4 d = __ldg(p + it * 32 + lane);
                float e = (d.x * d.x + d.y * d.y) * C_YX
                        + (d.z * d.z + d.w * d.w) * C_HW;
                float w = __expf(-e);
                sum_w += w;
                wrow[it * 32 + lane] = __float2half_rn(w);
            }
        }
        __syncthreads();
        // combine: fragment (tt,ss) holds G(t0+tt, s0+ss); needs w[tt][ss]
#pragma unroll
        for (int mi = 0; mi < 4; mi++) {
            const int tt = wm * 64 + mi * 16 + g;
#pragma unroll
            for (int ni = 0; ni < 4; ni++) {
                const int ss = wn * 32 + ni * 8 + 2 * tg;
                const float* a = acc[mi * 4 + ni];
                float2 f0 = __half22float2(*(const __half2*)&smW[tt * WSTR + ss]);
                float2 f1 = __half22float2(*(const __half2*)&smW[(tt + 8) * WSTR + ss]);
                sum_wg += f0.x * a[0] + f0.y * a[1] + f1.x * a[2] + f1.y * a[3];
            }
        }
    }

    // ================= Phase 3: transposed tile dT(j,i), i != j ==============
    if (ti != tj) {
        __syncthreads();   // combine reads done before w overwrite
        const size_t dbase = (size_t)b * TT * TT + (size_t)s0 * TT + t0;
#pragma unroll 4
        for (int r = 0; r < 16; r++) {
            const int row = warp * 16 + r;        // row = s-local
            const float4* p = dT4 + dbase + (size_t)row * TT;
            __half* wrow = smW + row * WSTR;      // smW[s_local][t_local]
#pragma unroll
            for (int it = 0; it < 4; it++) {
                float4 d = __ldg(p + it * 32 + lane);
                float e = (d.x * d.x + d.y * d.y) * C_YX
                        + (d.z * d.z + d.w * d.w) * C_HW;
                float w = __expf(-e);
                sum_w += w;
                wrow[it * 32 + lane] = __float2half_rn(w);
            }
        }
        __syncthreads();
        // combine: fragment (tt,ss) holds G(t0+tt,s0+ss)=G(s0+ss,t0+tt); needs w2[ss][tt]
#pragma unroll
        for (int mi = 0; mi < 4; mi++) {
            const int tt = wm * 64 + mi * 16 + g;
#pragma unroll
            for (int ni = 0; ni < 4; ni++) {
                const int ss = wn * 32 + ni * 8 + 2 * tg;
                const float* a = acc[mi * 4 + ni];
                float w0 = __half2float(smW[ss * WSTR + tt]);
                float w1 = __half2float(smW[(ss + 1) * WSTR + tt]);
                float w2 = __half2float(smW[ss * WSTR + tt + 8]);
                float w3 = __half2float(smW[(ss + 1) * WSTR + tt + 8]);
                sum_wg += w0 * a[0] + w1 * a[1] + w2 * a[2] + w3 * a[3];
            }
        }
    }

    // ================= reduce + accumulate ===================================
#pragma unroll
    for (int o = 16; o > 0; o >>= 1) {
        sum_w  += __shfl_down_sync(0xFFFFFFFFu, sum_w,  o);
        sum_wg += __shfl_down_sync(0xFFFFFFFFu, sum_wg, o);
    }
    __syncthreads();   // red[] overlays nothing, but order vs smW reads above
    if (lane == 0) { red[warp] = sum_w; red[8 + warp] = sum_wg; }
    __syncthreads();
    if (tid == 0) {
        float W = 0.0f, WG = 0.0f;
#pragma unroll
        for (int i = 0; i < 8; i++) { W += red[i]; WG += red[8 + i]; }
        atomicAdd(&g_den[b], W);
        atomicAdd(&g_num[b], 2.0f * (W - WG));
    }
}

// ---------------------------------------------------------------------------
// Finalize: mean over batches of num / max(den, 1e-6)
// ---------------------------------------------------------------------------
__global__ void final_kernel(float* __restrict__ out) {
    int lane = threadIdx.x;
    float r = 0.0f;
    if (lane < BB) r = g_num[lane] / fmaxf(g_den[lane], 1e-6f);
#pragma unroll
    for (int o = 16; o > 0; o >>= 1) r += __shfl_down_sync(0xFFFFFFFFu, r, o);
    if (lane == 0) out[0] = r * (1.0f / BB);
}

extern "C" void kernel_launch(void* const* d_in, const int* in_sizes, int n_in,
                              void* d_out, int out_size) {
    const float* z  = (const float*)d_in[0];
    const float* dT = (const float*)d_in[1];
    // Defensive: z has B*T*D = 4.19M elems, gt_dT has B*T*T*4 = 67.1M.
    if (n_in >= 2 && in_sizes[0] > in_sizes[1]) {
        const float* tmp = z; z = dT; dT = tmp;
    }
    (void)out_size;

    cudaFuncSetAttribute(fused_kernel,
                         cudaFuncAttributeMaxDynamicSharedMemorySize, SMEM_TOTAL);

    prep_kernel<<<1024, 256>>>((const float4*)z);

    fused_kernel<<<BB * NPAIR, 256, SMEM_TOTAL>>>((const float4*)dT);

    final_kernel<<<1, 32>>>((float*)d_out);
}